// round 4
// baseline (speedup 1.0000x reference)
#include <cuda_runtime.h>
#include <math.h>

#define BB 64
#define KP1 1024
#define D_IN 2048
#define D_PROJ 512
#define N_MEM 81920
#define TEMP 0.07f
#define MOM 0.5f

// ---------------- device scratch (no allocations allowed) ----------------
__device__ float g_fproj[BB * D_PROJ];   // normalized projected queries
__device__ float g_u[BB * D_IN];         // u_b = W^T f_b
__device__ float g_c[BB];                // c_b = bias . f_b
__device__ float g_normsq[N_MEM];        // ||W m + bias||^2 for flagged rows
__device__ int   g_flag[N_MEM];
__device__ int   g_uniq[N_MEM];
__device__ int   g_count;

// ---------------- reset flags / counter (every call: determinism) --------
__global__ void k_reset() {
    int i = blockIdx.x * blockDim.x + threadIdx.x;
    if (i < N_MEM) g_flag[i] = 0;
    if (i == 0) g_count = 0;
}

// ---------------- feat_proj = l2norm(feat @ W^T + bias), + c_b -----------
__global__ void k_fproj(const float* __restrict__ feat,
                        const float* __restrict__ W,
                        const float* __restrict__ bias) {
    __shared__ float sfeat[D_IN];
    __shared__ float sproj[D_PROJ];
    __shared__ float rss[8], rsb[8];
    __shared__ float s_rinv, s_c;

    int b = blockIdx.x;
    int t = threadIdx.x;
    int lane = t & 31, warp = t >> 5;

    const float4* f4 = (const float4*)(feat + (size_t)b * D_IN);
    float4* s4 = (float4*)sfeat;
    s4[t]       = f4[t];
    s4[t + 256] = f4[t + 256];
    __syncthreads();

    // each warp computes 64 projection components (coalesced W row reads)
    for (int pi = 0; pi < 64; pi++) {
        int p = warp * 64 + pi;
        const float4* wr = (const float4*)(W + (size_t)p * D_IN);
        float sum = 0.f;
        #pragma unroll
        for (int i = 0; i < 16; i++) {
            float4 wv = wr[lane + i * 32];
            float4 fv = s4[lane + i * 32];
            sum += wv.x * fv.x + wv.y * fv.y + wv.z * fv.z + wv.w * fv.w;
        }
        #pragma unroll
        for (int o = 16; o > 0; o >>= 1) sum += __shfl_xor_sync(0xffffffffu, sum, o);
        if (lane == 0) sproj[p] = sum;
    }
    __syncthreads();

    float v1 = sproj[t], v2 = sproj[t + 256];
    float ss = v1 * v1 + v2 * v2;
    float sb = bias[t] * v1 + bias[t + 256] * v2;
    #pragma unroll
    for (int o = 16; o > 0; o >>= 1) {
        ss += __shfl_xor_sync(0xffffffffu, ss, o);
        sb += __shfl_xor_sync(0xffffffffu, sb, o);
    }
    if (lane == 0) { rss[warp] = ss; rsb[warp] = sb; }
    __syncthreads();
    if (t == 0) {
        float a = 0.f, c = 0.f;
        for (int i = 0; i < 8; i++) { a += rss[i]; c += rsb[i]; }
        float rinv = 1.0f / sqrtf(a);
        s_rinv = rinv;
        s_c = c * rinv;
    }
    __syncthreads();
    float rinv = s_rinv;
    g_fproj[b * D_PROJ + t]       = v1 * rinv;
    g_fproj[b * D_PROJ + t + 256] = v2 * rinv;
    if (t == 0) g_c[b] = s_c;
}

// ---------------- u_b = W^T f_b  (per-batch GEMV, coalesced cols) --------
__global__ void k_u(const float* __restrict__ W) {
    __shared__ float sf[D_PROJ];
    int b = blockIdx.y;
    int t = threadIdx.x;
    int d = blockIdx.x * 256 + t;
    sf[t]       = g_fproj[b * D_PROJ + t];
    sf[t + 256] = g_fproj[b * D_PROJ + t + 256];
    __syncthreads();
    float sum = 0.f;
    #pragma unroll 4
    for (int p = 0; p < D_PROJ; p++)
        sum = fmaf(sf[p], W[(size_t)p * D_IN + d], sum);
    g_u[b * D_IN + d] = sum;
}

// ---------------- flag unique idx rows + compact ------------------------
__global__ void k_flag(const int* __restrict__ idx) {
    int i = blockIdx.x * blockDim.x + threadIdx.x;
    if (i >= BB * KP1) return;
    int row = idx[i];
    if (atomicExch(&g_flag[row], 1) == 0) {
        int pos = atomicAdd(&g_count, 1);
        g_uniq[pos] = row;
        g_normsq[row] = 0.f;
    }
}

// ---------------- norms: 128x128x8 tiled SGEMM -> rowwise sum of squares -
__global__ __launch_bounds__(256)
void k_norm(const float* __restrict__ mem,
            const float* __restrict__ W,
            const float* __restrict__ bias) {
    int cnt = g_count;
    int m0 = blockIdx.y * 128;
    if (m0 >= cnt) return;
    int n0 = blockIdx.x * 128;

    __shared__ float As[8][128];
    __shared__ float Bs[8][128];
    __shared__ int   srow[128];
    __shared__ float sbias[128];

    int t = threadIdx.x;
    if (t < 128) {
        int g = m0 + t;
        srow[t]  = g_uniq[(g < cnt) ? g : m0];
        sbias[t] = bias[n0 + t];
    }
    __syncthreads();

    int tx = t & 15, ty = t >> 4;
    int lm = t >> 1;
    int koff = (t & 1) * 4;
    const float* arow = mem + (size_t)srow[lm] * D_IN + koff;
    const float* brow = W + (size_t)(n0 + lm) * D_IN + koff;

    float acc[8][8];
    #pragma unroll
    for (int i = 0; i < 8; i++)
        #pragma unroll
        for (int j = 0; j < 8; j++) acc[i][j] = 0.f;

    for (int kc = 0; kc < D_IN; kc += 8) {
        float4 av = *(const float4*)(arow + kc);
        float4 bv = *(const float4*)(brow + kc);
        As[koff + 0][lm] = av.x; As[koff + 1][lm] = av.y;
        As[koff + 2][lm] = av.z; As[koff + 3][lm] = av.w;
        Bs[koff + 0][lm] = bv.x; Bs[koff + 1][lm] = bv.y;
        Bs[koff + 2][lm] = bv.z; Bs[koff + 3][lm] = bv.w;
        __syncthreads();
        #pragma unroll
        for (int k = 0; k < 8; k++) {
            float4 a0 = *(const float4*)&As[k][ty * 4];
            float4 a1 = *(const float4*)&As[k][64 + ty * 4];
            float4 b0 = *(const float4*)&Bs[k][tx * 4];
            float4 b1 = *(const float4*)&Bs[k][64 + tx * 4];
            float a[8]  = {a0.x, a0.y, a0.z, a0.w, a1.x, a1.y, a1.z, a1.w};
            float bb[8] = {b0.x, b0.y, b0.z, b0.w, b1.x, b1.y, b1.z, b1.w};
            #pragma unroll
            for (int i = 0; i < 8; i++)
                #pragma unroll
                for (int j = 0; j < 8; j++)
                    acc[i][j] = fmaf(a[i], bb[j], acc[i][j]);
        }
        __syncthreads();
    }

    // epilogue: (acc + bias)^2, reduce across tx (half-warp), one atomic/row
    #pragma unroll
    for (int i = 0; i < 8; i++) {
        int m = (i < 4) ? (ty * 4 + i) : (64 + ty * 4 + (i - 4));
        if (m0 + m < cnt) {
            float part = 0.f;
            #pragma unroll
            for (int j = 0; j < 8; j++) {
                int c = (j < 4) ? (tx * 4 + j) : (64 + tx * 4 + (j - 4));
                float v = acc[i][j] + sbias[c];
                part = fmaf(v, v, part);
            }
            #pragma unroll
            for (int o = 1; o < 16; o <<= 1)
                part += __shfl_xor_sync(0xffffffffu, part, o);
            if (tx == 0) atomicAdd(&g_normsq[srow[m]], part);
        }
    }
}

// ---------------- out[b,k] = (m.u_b + c_b) / (sqrt(normsq) * T) ----------
__global__ void k_out(const float* __restrict__ mem,
                      const int* __restrict__ idx,
                      float* __restrict__ out) {
    __shared__ float su[D_IN];
    int b = blockIdx.y;
    int kbase = blockIdx.x * 32;
    int t = threadIdx.x, lane = t & 31, warp = t >> 5;

    float4* su4 = (float4*)su;
    const float4* u4 = (const float4*)(g_u + (size_t)b * D_IN);
    su4[t]       = u4[t];
    su4[t + 256] = u4[t + 256];
    __syncthreads();
    float c = g_c[b];

    for (int j = 0; j < 4; j++) {
        int k = kbase + warp + 8 * j;
        int row = idx[b * KP1 + k];
        const float4* m4 = (const float4*)(mem + (size_t)row * D_IN);
        float sum = 0.f;
        #pragma unroll
        for (int i = 0; i < 16; i++) {
            float4 mv = m4[lane + i * 32];
            float4 uv = su4[lane + i * 32];
            sum += mv.x * uv.x + mv.y * uv.y + mv.z * uv.z + mv.w * uv.w;
        }
        #pragma unroll
        for (int o = 16; o > 0; o >>= 1) sum += __shfl_xor_sync(0xffffffffu, sum, o);
        if (lane == 0) {
            float num = sum + c;
            out[b * KP1 + k] = num / (sqrtf(g_normsq[row]) * TEMP);
        }
    }
}

// ---------------- momentum update (sequential i => JAX last-wins) --------
__global__ void k_update(const float* __restrict__ mem,
                         const float* __restrict__ feat,
                         const int* __restrict__ y,
                         float* __restrict__ newmem) {
    int d = blockIdx.x * blockDim.x + threadIdx.x;  // 0..2047
    for (int i = 0; i < BB; i++) {
        int row = y[i];
        newmem[(size_t)row * D_IN + d] =
            MOM * mem[(size_t)row * D_IN + d] + (1.0f - MOM) * feat[i * D_IN + d];
    }
}

// ---------------- launch -------------------------------------------------
extern "C" void kernel_launch(void* const* d_in, const int* in_sizes, int n_in,
                              void* d_out, int out_size) {
    const float* feat = (const float*)d_in[0];
    const int*   y    = (const int*)d_in[1];
    const int*   idx  = (const int*)d_in[2];
    const float* mem  = (const float*)d_in[3];
    const float* W    = (const float*)d_in[4];
    const float* bias = (const float*)d_in[5];

    float* out = (float*)d_out;
    float* newmem = out + (size_t)BB * KP1;

    // bulk copy of memory into output region (overlaps with compute queueing)
    cudaMemcpyAsync(newmem, mem, (size_t)N_MEM * D_IN * sizeof(float),
                    cudaMemcpyDeviceToDevice, 0);

    k_reset<<<(N_MEM + 255) / 256, 256>>>();
    k_fproj<<<BB, 256>>>(feat, W, bias);
    {
        dim3 g(D_IN / 256, BB);
        k_u<<<g, 256>>>(W);
    }
    k_flag<<<(BB * KP1 + 255) / 256, 256>>>(idx);
    {
        dim3 g(D_PROJ / 128, (N_MEM + 127) / 128);
        k_norm<<<g, 256>>>(mem, W, bias);
    }
    {
        dim3 g(KP1 / 32, BB);
        k_out<<<g, 256>>>(mem, idx, out);
    }
    k_update<<<D_IN / 256, 256>>>(mem, feat, y, newmem);
}

// round 10
// speedup vs baseline: 1.1611x; 1.1611x over previous
#include <cuda_runtime.h>
#include <math.h>
#include <stdint.h>

#define BB 64
#define KP1 1024
#define D_IN 2048
#define D_PROJ 512
#define N_MEM 81920
#define TEMP 0.07f
#define MOM 0.5f

// ---------------- device scratch (no allocations allowed) ----------------
__device__ float g_fproj[BB * D_PROJ];   // normalized projected queries
__device__ float g_u[BB * D_IN];         // u_b = W^T f_b
__device__ float g_c[BB];                // c_b = bias . f_proj_b
__device__ float g_normsq[N_MEM];        // ||W m + bias||^2 for flagged rows
__device__ int   g_flag[N_MEM];
__device__ int   g_uniq[N_MEM];
__device__ int   g_count;

// ---------------- tf32 helpers (sm_80+ family-safe) ----------------------
__device__ __forceinline__ float tf32r(float x) {
    uint32_t r;
    asm("cvt.rna.tf32.f32 %0, %1;" : "=r"(r) : "f"(x));
    return __uint_as_float(r);
}

__device__ __forceinline__ void mma8(float c[4], const uint32_t a[4],
                                     const uint32_t b[2]) {
    asm volatile(
        "mma.sync.aligned.m16n8k8.row.col.f32.tf32.tf32.f32 "
        "{%0,%1,%2,%3}, {%4,%5,%6,%7}, {%8,%9}, {%0,%1,%2,%3};"
        : "+f"(c[0]), "+f"(c[1]), "+f"(c[2]), "+f"(c[3])
        : "r"(a[0]), "r"(a[1]), "r"(a[2]), "r"(a[3]), "r"(b[0]), "r"(b[1]));
}

// ==================== k_norm_mma SMEM layout (floats) ====================
#define KC 32
#define NST (D_IN / KC)                 // 64
#define LDS_STRIDE 36                   // pad: frag LDS conflict-free
#define TILE_FLOATS (128 * LDS_STRIDE)  // 4608
#define A_OFF_F 0
#define B_OFF_F (2 * TILE_FLOATS)       // 9216
#define SROW_OFF_F (4 * TILE_FLOATS)    // 18432
#define SBIAS_OFF_F (SROW_OFF_F + 128)
#define SMEM_FLOATS (SBIAS_OFF_F + 128)
#define SMEM_BYTES (SMEM_FLOATS * 4)    // 74752

// ---------------- reset flags / counter ----------------------------------
__global__ void k_reset() {
    int i = blockIdx.x * blockDim.x + threadIdx.x;
    if (i < N_MEM) g_flag[i] = 0;
    if (i == 0) g_count = 0;
}

// ---------------- feat_proj = l2norm(feat @ W^T + bias), + c_b -----------
__global__ void k_fproj(const float* __restrict__ feat,
                        const float* __restrict__ W,
                        const float* __restrict__ bias) {
    __shared__ float sfeat[D_IN];
    __shared__ float sproj[D_PROJ];
    __shared__ float rss[8], rsb[8];
    __shared__ float s_rinv, s_c;

    int b = blockIdx.x;
    int t = threadIdx.x;
    int lane = t & 31, warp = t >> 5;

    const float4* f4 = (const float4*)(feat + (size_t)b * D_IN);
    float4* s4 = (float4*)sfeat;
    s4[t]       = f4[t];
    s4[t + 256] = f4[t + 256];
    __syncthreads();

    for (int pi = 0; pi < 64; pi++) {
        int p = warp * 64 + pi;
        const float4* wr = (const float4*)(W + (size_t)p * D_IN);
        float sum = 0.f;
        #pragma unroll
        for (int i = 0; i < 16; i++) {
            float4 wv = wr[lane + i * 32];
            float4 fv = s4[lane + i * 32];
            sum += wv.x * fv.x + wv.y * fv.y + wv.z * fv.z + wv.w * fv.w;
        }
        #pragma unroll
        for (int o = 16; o > 0; o >>= 1) sum += __shfl_xor_sync(0xffffffffu, sum, o);
        if (lane == 0) sproj[p] = sum;
    }
    __syncthreads();

    float v1 = sproj[t], v2 = sproj[t + 256];
    float ss = v1 * v1 + v2 * v2;
    float sb = bias[t] * v1 + bias[t + 256] * v2;
    #pragma unroll
    for (int o = 16; o > 0; o >>= 1) {
        ss += __shfl_xor_sync(0xffffffffu, ss, o);
        sb += __shfl_xor_sync(0xffffffffu, sb, o);
    }
    if (lane == 0) { rss[warp] = ss; rsb[warp] = sb; }
    __syncthreads();
    if (t == 0) {
        float a = 0.f, c = 0.f;
        for (int i = 0; i < 8; i++) { a += rss[i]; c += rsb[i]; }
        float rinv = 1.0f / sqrtf(a);
        s_rinv = rinv;
        s_c = c * rinv;
    }
    __syncthreads();
    float rinv = s_rinv;
    g_fproj[b * D_PROJ + t]       = v1 * rinv;
    g_fproj[b * D_PROJ + t + 256] = v2 * rinv;
    if (t == 0) g_c[b] = s_c;
}

// ---------------- u_b = W^T f_b ------------------------------------------
__global__ void k_u(const float* __restrict__ W) {
    __shared__ float sf[D_PROJ];
    int b = blockIdx.y;
    int t = threadIdx.x;
    int d = blockIdx.x * 256 + t;
    sf[t]       = g_fproj[b * D_PROJ + t];
    sf[t + 256] = g_fproj[b * D_PROJ + t + 256];
    __syncthreads();
    float sum = 0.f;
    #pragma unroll 4
    for (int p = 0; p < D_PROJ; p++)
        sum = fmaf(sf[p], W[(size_t)p * D_IN + d], sum);
    g_u[b * D_IN + d] = sum;
}

// ---------------- flag unique idx rows + compact --------------------------
__global__ void k_flag(const int* __restrict__ idx) {
    int i = blockIdx.x * blockDim.x + threadIdx.x;
    if (i >= BB * KP1) return;
    int row = idx[i];
    if (atomicExch(&g_flag[row], 1) == 0) {
        int pos = atomicAdd(&g_count, 1);
        g_uniq[pos] = row;
        g_normsq[row] = 0.f;   // epilogue accumulates via atomicAdd
    }
}

// ---------------- staging: global -> SMEM (tf32, rna rounding) ------------
__device__ __forceinline__ void stage_tiles(const float* __restrict__ mem,
                                            const float* __restrict__ W,
                                            const int* __restrict__ srow,
                                            float* sm, int buf, int koff,
                                            int n0, int t) {
    float* sA = sm + A_OFF_F + buf * TILE_FLOATS;
    float* sB = sm + B_OFF_F + buf * TILE_FLOATS;
    #pragma unroll
    for (int q = 0; q < 8; q++) {
        int i = q * 128 + t;       // 0..1023 float4 slots
        int row = i >> 3, seg = i & 7;
        float4 v = *(const float4*)(mem + (size_t)srow[row] * D_IN + koff + seg * 4);
        float* d = sA + row * LDS_STRIDE + seg * 4;
        d[0] = tf32r(v.x); d[1] = tf32r(v.y); d[2] = tf32r(v.z); d[3] = tf32r(v.w);
        float4 w = *(const float4*)(W + (size_t)(n0 + row) * D_IN + koff + seg * 4);
        float* db = sB + row * LDS_STRIDE + seg * 4;
        db[0] = tf32r(w.x); db[1] = tf32r(w.y); db[2] = tf32r(w.z); db[3] = tf32r(w.w);
    }
}

// ---------------- norms via mma.sync tf32: CTA 128x128, warp 64x64 --------
__global__ void __launch_bounds__(128, 2)
k_norm_mma(const float* __restrict__ mem, const float* __restrict__ W,
           const float* __restrict__ bias) {
    extern __shared__ float sm[];
    int cnt = g_count;
    int m0 = blockIdx.y * 128;
    if (m0 >= cnt) return;
    int n0 = blockIdx.x * 128;

    int t = threadIdx.x, lane = t & 31, warp = t >> 5;
    int wm = warp >> 1, wn = warp & 1;       // 2x2 warp grid
    int gid = lane >> 2, tig = lane & 3;

    int*   srow  = (int*)(sm + SROW_OFF_F);
    float* sbias = sm + SBIAS_OFF_F;
    {
        int g = m0 + t;
        srow[t]  = g_uniq[(g < cnt) ? g : m0];
        sbias[t] = bias[n0 + t];
    }
    __syncthreads();

    float c[4][8][4];
    #pragma unroll
    for (int mi = 0; mi < 4; mi++)
        #pragma unroll
        for (int ni = 0; ni < 8; ni++)
            #pragma unroll
            for (int j = 0; j < 4; j++) c[mi][ni][j] = 0.f;

    stage_tiles(mem, W, srow, sm, 0, 0, n0, t);
    __syncthreads();

    for (int s = 0; s < NST; s++) {
        if (s + 1 < NST)
            stage_tiles(mem, W, srow, sm, (s + 1) & 1, (s + 1) * KC, n0, t);

        // compute on buffer s&1
        const uint32_t* A = (const uint32_t*)(sm + A_OFF_F + (s & 1) * TILE_FLOATS);
        const uint32_t* B = (const uint32_t*)(sm + B_OFF_F + (s & 1) * TILE_FLOATS);
        #pragma unroll
        for (int k8 = 0; k8 < KC / 8; k8++) {
            int kb = k8 * 8;
            uint32_t a[4][4], b[8][2];
            #pragma unroll
            for (int mi = 0; mi < 4; mi++) {
                int r = wm * 64 + mi * 16 + gid;
                a[mi][0] = A[r * LDS_STRIDE + kb + tig];
                a[mi][1] = A[(r + 8) * LDS_STRIDE + kb + tig];
                a[mi][2] = A[r * LDS_STRIDE + kb + tig + 4];
                a[mi][3] = A[(r + 8) * LDS_STRIDE + kb + tig + 4];
            }
            #pragma unroll
            for (int ni = 0; ni < 8; ni++) {
                int r = wn * 64 + ni * 8 + gid;
                b[ni][0] = B[r * LDS_STRIDE + kb + tig];
                b[ni][1] = B[r * LDS_STRIDE + kb + tig + 4];
            }
            #pragma unroll
            for (int mi = 0; mi < 4; mi++)
                #pragma unroll
                for (int ni = 0; ni < 8; ni++)
                    mma8(c[mi][ni], a[mi], b[ni]);
        }
        __syncthreads();
    }

    // epilogue: (acc + bias)^2, quad-reduce across tig, atomicAdd per row
    #pragma unroll
    for (int mi = 0; mi < 4; mi++) {
        #pragma unroll
        for (int h = 0; h < 2; h++) {
            int m = wm * 64 + mi * 16 + gid + h * 8;
            float part = 0.f;
            #pragma unroll
            for (int ni = 0; ni < 8; ni++) {
                #pragma unroll
                for (int j = 0; j < 2; j++) {
                    int n = wn * 64 + ni * 8 + tig * 2 + j;
                    float v = c[mi][ni][h * 2 + j] + sbias[n];
                    part = fmaf(v, v, part);
                }
            }
            part += __shfl_xor_sync(0xffffffffu, part, 1);
            part += __shfl_xor_sync(0xffffffffu, part, 2);
            if (tig == 0 && m0 + m < cnt)
                atomicAdd(&g_normsq[srow[m]], part);
        }
    }
}

// ---------------- out[b,k] = (m.u_b + c_b) / (sqrt(normsq) * T) ----------
__global__ void k_out(const float* __restrict__ mem,
                      const int* __restrict__ idx,
                      float* __restrict__ out) {
    __shared__ float su[D_IN];
    int b = blockIdx.y;
    int kbase = blockIdx.x * 32;
    int t = threadIdx.x, lane = t & 31, warp = t >> 5;

    float4* su4 = (float4*)su;
    const float4* u4 = (const float4*)(g_u + (size_t)b * D_IN);
    su4[t]       = u4[t];
    su4[t + 256] = u4[t + 256];
    __syncthreads();
    float c = g_c[b];

    for (int j = 0; j < 4; j++) {
        int k = kbase + warp + 8 * j;
        int row = idx[b * KP1 + k];
        const float4* m4 = (const float4*)(mem + (size_t)row * D_IN);
        float sum = 0.f;
        #pragma unroll
        for (int i = 0; i < 16; i++) {
            float4 mv = m4[lane + i * 32];
            float4 uv = su4[lane + i * 32];
            sum += mv.x * uv.x + mv.y * uv.y + mv.z * uv.z + mv.w * uv.w;
        }
        #pragma unroll
        for (int o = 16; o > 0; o >>= 1) sum += __shfl_xor_sync(0xffffffffu, sum, o);
        if (lane == 0) {
            float num = sum + c;
            out[b * KP1 + k] = num / (sqrtf(g_normsq[row]) * TEMP);
        }
    }
}

// ---------------- momentum update (sequential i => JAX last-wins) --------
__global__ void k_update(const float* __restrict__ mem,
                         const float* __restrict__ feat,
                         const int* __restrict__ y,
                         float* __restrict__ newmem) {
    int d = blockIdx.x * blockDim.x + threadIdx.x;  // 0..2047
    for (int i = 0; i < BB; i++) {
        int row = y[i];
        newmem[(size_t)row * D_IN + d] =
            MOM * mem[(size_t)row * D_IN + d] + (1.0f - MOM) * feat[i * D_IN + d];
    }
}

// ---------------- launch -------------------------------------------------
extern "C" void kernel_launch(void* const* d_in, const int* in_sizes, int n_in,
                              void* d_out, int out_size) {
    const float* feat = (const float*)d_in[0];
    const int*   y    = (const int*)d_in[1];
    const int*   idx  = (const int*)d_in[2];
    const float* mem  = (const float*)d_in[3];
    const float* W    = (const float*)d_in[4];
    const float* bias = (const float*)d_in[5];

    float* out = (float*)d_out;
    float* newmem = out + (size_t)BB * KP1;

    cudaMemcpyAsync(newmem, mem, (size_t)N_MEM * D_IN * sizeof(float),
                    cudaMemcpyDeviceToDevice, 0);

    k_reset<<<(N_MEM + 255) / 256, 256>>>();
    k_fproj<<<BB, 256>>>(feat, W, bias);
    {
        dim3 g(D_IN / 256, BB);
        k_u<<<g, 256>>>(W);
    }
    k_flag<<<(BB * KP1 + 255) / 256, 256>>>(idx);
    {
        cudaFuncSetAttribute(k_norm_mma,
                             cudaFuncAttributeMaxDynamicSharedMemorySize,
                             SMEM_BYTES);
        // worst case unique rows = 65536 -> 512 M-tiles; 4 N-tiles of 128
        dim3 g(4, 512);
        k_norm_mma<<<g, 128, SMEM_BYTES>>>(mem, W, bias);
    }
    {
        dim3 g(KP1 / 32, BB);
        k_out<<<g, 256>>>(mem, idx, out);
    }
    k_update<<<D_IN / 256, 256>>>(mem, feat, y, newmem);
}

// round 12
// speedup vs baseline: 1.7282x; 1.4885x over previous
#include <cuda_runtime.h>
#include <math.h>
#include <stdint.h>

#define BB 64
#define KP1 1024
#define D_IN 2048
#define D_PROJ 512
#define N_MEM 81920
#define TEMP 0.07f
#define MOM 0.5f

// ---------------- device scratch (no allocations allowed) ----------------
__device__ float g_fproj[BB * D_PROJ];   // normalized projected queries
__device__ float g_u[BB * D_IN];         // u_b = W^T f_b
__device__ float g_c[BB];                // c_b = bias . f_proj_b
__device__ float g_normsq[N_MEM];        // ||W m + bias||^2 for flagged rows
__device__ int   g_flag[N_MEM];
__device__ int   g_uniq[N_MEM];
__device__ int   g_count;

// ---------------- bf16 helpers -------------------------------------------
__device__ __forceinline__ uint32_t pk_bf16x2(float lo, float hi) {
    uint32_t r;
    asm("cvt.rn.bf16x2.f32 %0, %1, %2;" : "=r"(r) : "f"(hi), "f"(lo));
    return r;
}

__device__ __forceinline__ void mma16(float c[4], const uint32_t a[4],
                                      const uint32_t b[2]) {
    asm volatile(
        "mma.sync.aligned.m16n8k16.row.col.f32.bf16.bf16.f32 "
        "{%0,%1,%2,%3}, {%4,%5,%6,%7}, {%8,%9}, {%0,%1,%2,%3};"
        : "+f"(c[0]), "+f"(c[1]), "+f"(c[2]), "+f"(c[3])
        : "r"(a[0]), "r"(a[1]), "r"(a[2]), "r"(a[3]), "r"(b[0]), "r"(b[1]));
}

// ==================== k_norm_mma SMEM layout (u32 units) =================
// Per stage: KC=64 bf16 per row = 32 u32 per row, 128 rows per tile.
// Physical placement: word w of row r lives at r*32 + (((w>>2)^(r&7))<<2)+(w&3)
// -> conflict-free for uint4 staging stores AND all frag ld.shared.b32.
#define KC 64
#define NST (D_IN / KC)                 // 32
#define TILE_U32 (128 * 32)             // 4096
#define A_OFF_U 0                       // 2 buffers
#define B_OFF_U (2 * TILE_U32)          // 8192, 2 buffers
#define SROW_OFF_U (4 * TILE_U32)       // 16384
#define SBIAS_OFF_U (SROW_OFF_U + 128)
#define SMEM_U32 (SBIAS_OFF_U + 128)
#define SMEM_BYTES (SMEM_U32 * 4)       // 66560

__device__ __forceinline__ int smw(int row, int w) {
    return (row << 5) + (((((w) >> 2) ^ (row & 7)) << 2) | ((w) & 3));
}

// ---------------- reset flags / counter ----------------------------------
__global__ void k_reset() {
    int i = blockIdx.x * blockDim.x + threadIdx.x;
    if (i < N_MEM) g_flag[i] = 0;
    if (i == 0) g_count = 0;
}

// ---------------- feat_proj = l2norm(feat @ W^T + bias), + c_b -----------
__global__ void k_fproj(const float* __restrict__ feat,
                        const float* __restrict__ W,
                        const float* __restrict__ bias) {
    __shared__ float sfeat[D_IN];
    __shared__ float sproj[D_PROJ];
    __shared__ float rss[8], rsb[8];
    __shared__ float s_rinv, s_c;

    int b = blockIdx.x;
    int t = threadIdx.x;
    int lane = t & 31, warp = t >> 5;

    const float4* f4 = (const float4*)(feat + (size_t)b * D_IN);
    float4* s4 = (float4*)sfeat;
    s4[t]       = f4[t];
    s4[t + 256] = f4[t + 256];
    __syncthreads();

    for (int pi = 0; pi < 64; pi++) {
        int p = warp * 64 + pi;
        const float4* wr = (const float4*)(W + (size_t)p * D_IN);
        float sum = 0.f;
        #pragma unroll
        for (int i = 0; i < 16; i++) {
            float4 wv = wr[lane + i * 32];
            float4 fv = s4[lane + i * 32];
            sum += wv.x * fv.x + wv.y * fv.y + wv.z * fv.z + wv.w * fv.w;
        }
        #pragma unroll
        for (int o = 16; o > 0; o >>= 1) sum += __shfl_xor_sync(0xffffffffu, sum, o);
        if (lane == 0) sproj[p] = sum;
    }
    __syncthreads();

    float v1 = sproj[t], v2 = sproj[t + 256];
    float ss = v1 * v1 + v2 * v2;
    float sb = bias[t] * v1 + bias[t + 256] * v2;
    #pragma unroll
    for (int o = 16; o > 0; o >>= 1) {
        ss += __shfl_xor_sync(0xffffffffu, ss, o);
        sb += __shfl_xor_sync(0xffffffffu, sb, o);
    }
    if (lane == 0) { rss[warp] = ss; rsb[warp] = sb; }
    __syncthreads();
    if (t == 0) {
        float a = 0.f, c = 0.f;
        for (int i = 0; i < 8; i++) { a += rss[i]; c += rsb[i]; }
        float rinv = 1.0f / sqrtf(a);
        s_rinv = rinv;
        s_c = c * rinv;
    }
    __syncthreads();
    float rinv = s_rinv;
    g_fproj[b * D_PROJ + t]       = v1 * rinv;
    g_fproj[b * D_PROJ + t + 256] = v2 * rinv;
    if (t == 0) g_c[b] = s_c;
}

// ---------------- u_b = W^T f_b ------------------------------------------
__global__ void k_u(const float* __restrict__ W) {
    __shared__ float sf[D_PROJ];
    int b = blockIdx.y;
    int t = threadIdx.x;
    int d = blockIdx.x * 256 + t;
    sf[t]       = g_fproj[b * D_PROJ + t];
    sf[t + 256] = g_fproj[b * D_PROJ + t + 256];
    __syncthreads();
    float sum = 0.f;
    #pragma unroll 4
    for (int p = 0; p < D_PROJ; p++)
        sum = fmaf(sf[p], W[(size_t)p * D_IN + d], sum);
    g_u[b * D_IN + d] = sum;
}

// ---------------- flag unique idx rows + compact --------------------------
__global__ void k_flag(const int* __restrict__ idx) {
    int i = blockIdx.x * blockDim.x + threadIdx.x;
    if (i >= BB * KP1) return;
    int row = idx[i];
    if (atomicExch(&g_flag[row], 1) == 0) {
        int pos = atomicAdd(&g_count, 1);
        g_uniq[pos] = row;
        g_normsq[row] = 0.f;   // epilogue accumulates via atomicAdd
    }
}

// ---------------- staging: global fp32 -> SMEM bf16 (swizzled) -----------
__device__ __forceinline__ void stage_tiles(const float* __restrict__ mem,
                                            const float* __restrict__ W,
                                            const int* __restrict__ srow,
                                            uint32_t* sA, uint32_t* sB,
                                            int koff, int n0, int t) {
    #pragma unroll
    for (int q = 0; q < 8; q++) {
        int i = q * 128 + t;            // 1024 tasks = 128 rows x 8 segs
        int row = i >> 3, s = i & 7;
        int dst = (row << 5) + ((s ^ (row & 7)) << 2);
        const float* pa = mem + (size_t)srow[row] * D_IN + koff + s * 8;
        float4 v0 = *(const float4*)pa;
        float4 v1 = *(const float4*)(pa + 4);
        uint4 w;
        w.x = pk_bf16x2(v0.x, v0.y); w.y = pk_bf16x2(v0.z, v0.w);
        w.z = pk_bf16x2(v1.x, v1.y); w.w = pk_bf16x2(v1.z, v1.w);
        *(uint4*)(sA + dst) = w;
        const float* pb = W + (size_t)(n0 + row) * D_IN + koff + s * 8;
        v0 = *(const float4*)pb;
        v1 = *(const float4*)(pb + 4);
        w.x = pk_bf16x2(v0.x, v0.y); w.y = pk_bf16x2(v0.z, v0.w);
        w.z = pk_bf16x2(v1.x, v1.y); w.w = pk_bf16x2(v1.z, v1.w);
        *(uint4*)(sB + dst) = w;
    }
}

// ---------------- norms via mma.sync bf16: CTA 128x128, warp 64x64 --------
__global__ void __launch_bounds__(128, 2)
k_norm_mma(const float* __restrict__ mem, const float* __restrict__ W,
           const float* __restrict__ bias) {
    extern __shared__ uint32_t smu[];
    int cnt = g_count;
    int m0 = blockIdx.y * 128;
    if (m0 >= cnt) return;
    int n0 = blockIdx.x * 128;

    int t = threadIdx.x, lane = t & 31, warp = t >> 5;
    int wm = warp >> 1, wn = warp & 1;       // 2x2 warp grid
    int gid = lane >> 2, tig = lane & 3;

    int*   srow  = (int*)(smu + SROW_OFF_U);
    float* sbias = (float*)(smu + SBIAS_OFF_U);
    {
        int g = m0 + t;
        srow[t]  = g_uniq[(g < cnt) ? g : m0];
        sbias[t] = bias[n0 + t];
    }
    __syncthreads();

    float c[4][8][4];
    #pragma unroll
    for (int mi = 0; mi < 4; mi++)
        #pragma unroll
        for (int ni = 0; ni < 8; ni++)
            #pragma unroll
            for (int j = 0; j < 4; j++) c[mi][ni][j] = 0.f;

    stage_tiles(mem, W, srow, smu + A_OFF_U, smu + B_OFF_U, 0, n0, t);
    __syncthreads();

    for (int s = 0; s < NST; s++) {
        if (s + 1 < NST) {
            int nb = (s + 1) & 1;
            stage_tiles(mem, W, srow, smu + A_OFF_U + nb * TILE_U32,
                        smu + B_OFF_U + nb * TILE_U32, (s + 1) * KC, n0, t);
        }
        const uint32_t* A = smu + A_OFF_U + (s & 1) * TILE_U32;
        const uint32_t* B = smu + B_OFF_U + (s & 1) * TILE_U32;
        #pragma unroll
        for (int ks = 0; ks < KC / 16; ks++) {
            int kb = ks * 8;                 // u32 word base of this k16 step
            uint32_t a[4][4], b[8][2];
            #pragma unroll
            for (int mi = 0; mi < 4; mi++) {
                int ra = wm * 64 + mi * 16 + gid;
                a[mi][0] = A[smw(ra,     kb + tig)];
                a[mi][1] = A[smw(ra + 8, kb + tig)];
                a[mi][2] = A[smw(ra,     kb + tig + 4)];
                a[mi][3] = A[smw(ra + 8, kb + tig + 4)];
            }
            #pragma unroll
            for (int ni = 0; ni < 8; ni++) {
                int rb = wn * 64 + ni * 8 + gid;
                b[ni][0] = B[smw(rb, kb + tig)];
                b[ni][1] = B[smw(rb, kb + tig + 4)];
            }
            #pragma unroll
            for (int mi = 0; mi < 4; mi++)
                #pragma unroll
                for (int ni = 0; ni < 8; ni++)
                    mma16(c[mi][ni], a[mi], b[ni]);
        }
        __syncthreads();
    }

    // epilogue: (acc + bias)^2, quad-reduce across tig, atomicAdd per row
    #pragma unroll
    for (int mi = 0; mi < 4; mi++) {
        #pragma unroll
        for (int h = 0; h < 2; h++) {
            int m = wm * 64 + mi * 16 + gid + h * 8;
            float part = 0.f;
            #pragma unroll
            for (int ni = 0; ni < 8; ni++) {
                #pragma unroll
                for (int j = 0; j < 2; j++) {
                    int n = wn * 64 + ni * 8 + tig * 2 + j;
                    float v = c[mi][ni][h * 2 + j] + sbias[n];
                    part = fmaf(v, v, part);
                }
            }
            part += __shfl_xor_sync(0xffffffffu, part, 1);
            part += __shfl_xor_sync(0xffffffffu, part, 2);
            if (tig == 0 && m0 + m < cnt)
                atomicAdd(&g_normsq[srow[m]], part);
        }
    }
}

// ---------------- out[b,k] = (m.u_b + c_b) / (sqrt(normsq) * T) ----------
__global__ void k_out(const float* __restrict__ mem,
                      const int* __restrict__ idx,
                      float* __restrict__ out) {
    __shared__ float su[D_IN];
    int b = blockIdx.y;
    int kbase = blockIdx.x * 32;
    int t = threadIdx.x, lane = t & 31, warp = t >> 5;

    float4* su4 = (float4*)su;
    const float4* u4 = (const float4*)(g_u + (size_t)b * D_IN);
    su4[t]       = u4[t];
    su4[t + 256] = u4[t + 256];
    __syncthreads();
    float c = g_c[b];

    for (int j = 0; j < 4; j++) {
        int k = kbase + warp + 8 * j;
        int row = idx[b * KP1 + k];
        const float4* m4 = (const float4*)(mem + (size_t)row * D_IN);
        float sum = 0.f;
        #pragma unroll
        for (int i = 0; i < 16; i++) {
            float4 mv = m4[lane + i * 32];
            float4 uv = su4[lane + i * 32];
            sum += mv.x * uv.x + mv.y * uv.y + mv.z * uv.z + mv.w * uv.w;
        }
        #pragma unroll
        for (int o = 16; o > 0; o >>= 1) sum += __shfl_xor_sync(0xffffffffu, sum, o);
        if (lane == 0) {
            float num = sum + c;
            out[b * KP1 + k] = num / (sqrtf(g_normsq[row]) * TEMP);
        }
    }
}

// ---------------- momentum update (sequential i => JAX last-wins) --------
__global__ void k_update(const float* __restrict__ mem,
                         const float* __restrict__ feat,
                         const int* __restrict__ y,
                         float* __restrict__ newmem) {
    int d = blockIdx.x * blockDim.x + threadIdx.x;  // 0..2047
    for (int i = 0; i < BB; i++) {
        int row = y[i];
        newmem[(size_t)row * D_IN + d] =
            MOM * mem[(size_t)row * D_IN + d] + (1.0f - MOM) * feat[i * D_IN + d];
    }
}

// ---------------- launch -------------------------------------------------
extern "C" void kernel_launch(void* const* d_in, const int* in_sizes, int n_in,
                              void* d_out, int out_size) {
    const float* feat = (const float*)d_in[0];
    const int*   y    = (const int*)d_in[1];
    const int*   idx  = (const int*)d_in[2];
    const float* mem  = (const float*)d_in[3];
    const float* W    = (const float*)d_in[4];
    const float* bias = (const float*)d_in[5];

    float* out = (float*)d_out;
    float* newmem = out + (size_t)BB * KP1;

    cudaMemcpyAsync(newmem, mem, (size_t)N_MEM * D_IN * sizeof(float),
                    cudaMemcpyDeviceToDevice, 0);

    k_reset<<<(N_MEM + 255) / 256, 256>>>();
    k_fproj<<<BB, 256>>>(feat, W, bias);
    {
        dim3 g(D_IN / 256, BB);
        k_u<<<g, 256>>>(W);
    }
    k_flag<<<(BB * KP1 + 255) / 256, 256>>>(idx);
    {
        cudaFuncSetAttribute(k_norm_mma,
                             cudaFuncAttributeMaxDynamicSharedMemorySize,
                             SMEM_BYTES);
        // worst case unique rows = 65536 -> 512 M-tiles; 4 N-tiles of 128
        dim3 g(4, 512);
        k_norm_mma<<<g, 128, SMEM_BYTES>>>(mem, W, bias);
    }
    {
        dim3 g(KP1 / 32, BB);
        k_out<<<g, 256>>>(mem, idx, out);
    }
    k_update<<<D_IN / 256, 256>>>(mem, feat, y, newmem);
}

// round 13
// speedup vs baseline: 1.9240x; 1.1132x over previous
#include <cuda_runtime.h>
#include <math.h>
#include <stdint.h>

#define BB 64
#define KP1 1024
#define D_IN 2048
#define D_PROJ 512
#define N_MEM 81920
#define TEMP 0.07f
#define MOM 0.5f

// ---------------- device scratch (no allocations allowed) ----------------
__device__ float g_fproj[BB * D_PROJ];   // normalized projected queries
__device__ float g_u[BB * D_IN];         // u_b = W^T f_b
__device__ float g_c[BB];                // c_b = bias . f_proj_b
__device__ float g_normsq[N_MEM];        // ||W m + bias||^2 for flagged rows
__device__ int   g_flag[N_MEM];
__device__ int   g_uniq[N_MEM];
__device__ int   g_count;
__device__ uint4 g_WB4[(D_PROJ * D_IN) / 8];   // W in bf16, row-major (2 MB)

// ---------------- helpers -------------------------------------------------
__device__ __forceinline__ uint32_t pk_bf16x2(float lo, float hi) {
    uint32_t r;
    asm("cvt.rn.bf16x2.f32 %0, %1, %2;" : "=r"(r) : "f"(hi), "f"(lo));
    return r;
}
__device__ __forceinline__ uint32_t smem_u32(const void* p) {
    uint32_t a;
    asm("{ .reg .u64 t; cvta.to.shared.u64 t, %1; cvt.u32.u64 %0, t; }"
        : "=r"(a) : "l"(p));
    return a;
}
__device__ __forceinline__ void mma16(float c[4], const uint32_t a[4],
                                      const uint32_t b0, const uint32_t b1) {
    asm volatile(
        "mma.sync.aligned.m16n8k16.row.col.f32.bf16.bf16.f32 "
        "{%0,%1,%2,%3}, {%4,%5,%6,%7}, {%8,%9}, {%0,%1,%2,%3};"
        : "+f"(c[0]), "+f"(c[1]), "+f"(c[2]), "+f"(c[3])
        : "r"(a[0]), "r"(a[1]), "r"(a[2]), "r"(a[3]), "r"(b0), "r"(b1));
}
__device__ __forceinline__ void ldm4(uint32_t r[4], uint32_t addr) {
    asm volatile("ldmatrix.sync.aligned.m8n8.x4.shared.b16 {%0,%1,%2,%3}, [%4];"
        : "=r"(r[0]), "=r"(r[1]), "=r"(r[2]), "=r"(r[3]) : "r"(addr));
}
#define CP_ASYNC16(dst, src) \
    asm volatile("cp.async.cg.shared.global [%0], [%1], 16;" :: "r"(dst), "l"(src))
#define CP_COMMIT() asm volatile("cp.async.commit_group;" ::: "memory")
#define CP_WAIT1() asm volatile("cp.async.wait_group 1;" ::: "memory")
#define CP_WAIT0() asm volatile("cp.async.wait_group 0;" ::: "memory")

// ==================== k_norm_mma SMEM layout ==============================
// Per stage: KC=64 bf16 per row = 128 B per row (8 granules of 16 B), 128 rows.
// Granule g of row r lives at physical granule (g ^ (r&7)) within the row.
#define KC 64
#define NST (D_IN / KC)                 // 32
#define TILE_BYTES 16384                // 128 rows x 128 B
#define A_OFF 0                         // 2 buffers
#define B_OFF (2 * TILE_BYTES)          // 32768, 2 buffers
#define SROW_OFF (4 * TILE_BYTES)       // 65536
#define SBIAS_OFF (SROW_OFF + 512)
#define SMEM_BYTES (SBIAS_OFF + 512)    // 66560

// ---------------- reset flags / counter ----------------------------------
__global__ void k_reset() {
    int i = blockIdx.x * blockDim.x + threadIdx.x;
    if (i < N_MEM) g_flag[i] = 0;
    if (i == 0) g_count = 0;
}

// ---------------- W -> bf16 (row-major), once per call --------------------
__global__ void k_prepW(const float* __restrict__ W) {
    int r = blockIdx.x, t = threadIdx.x;
    const float4* src = (const float4*)(W + (size_t)r * D_IN);
    float4 v0 = src[2 * t], v1 = src[2 * t + 1];
    uint4 w;
    w.x = pk_bf16x2(v0.x, v0.y); w.y = pk_bf16x2(v0.z, v0.w);
    w.z = pk_bf16x2(v1.x, v1.y); w.w = pk_bf16x2(v1.z, v1.w);
    g_WB4[r * (D_IN / 8) + t] = w;
}

// ---------------- feat_proj = l2norm(feat @ W^T + bias), + c_b -----------
__global__ void k_fproj(const float* __restrict__ feat,
                        const float* __restrict__ W,
                        const float* __restrict__ bias) {
    __shared__ float sfeat[D_IN];
    __shared__ float sproj[D_PROJ];
    __shared__ float rss[8], rsb[8];
    __shared__ float s_rinv, s_c;

    int b = blockIdx.x;
    int t = threadIdx.x;
    int lane = t & 31, warp = t >> 5;

    const float4* f4 = (const float4*)(feat + (size_t)b * D_IN);
    float4* s4 = (float4*)sfeat;
    s4[t]       = f4[t];
    s4[t + 256] = f4[t + 256];
    __syncthreads();

    for (int pi = 0; pi < 64; pi++) {
        int p = warp * 64 + pi;
        const float4* wr = (const float4*)(W + (size_t)p * D_IN);
        float sum = 0.f;
        #pragma unroll
        for (int i = 0; i < 16; i++) {
            float4 wv = wr[lane + i * 32];
            float4 fv = s4[lane + i * 32];
            sum += wv.x * fv.x + wv.y * fv.y + wv.z * fv.z + wv.w * fv.w;
        }
        #pragma unroll
        for (int o = 16; o > 0; o >>= 1) sum += __shfl_xor_sync(0xffffffffu, sum, o);
        if (lane == 0) sproj[p] = sum;
    }
    __syncthreads();

    float v1 = sproj[t], v2 = sproj[t + 256];
    float ss = v1 * v1 + v2 * v2;
    float sb = bias[t] * v1 + bias[t + 256] * v2;
    #pragma unroll
    for (int o = 16; o > 0; o >>= 1) {
        ss += __shfl_xor_sync(0xffffffffu, ss, o);
        sb += __shfl_xor_sync(0xffffffffu, sb, o);
    }
    if (lane == 0) { rss[warp] = ss; rsb[warp] = sb; }
    __syncthreads();
    if (t == 0) {
        float a = 0.f, c = 0.f;
        for (int i = 0; i < 8; i++) { a += rss[i]; c += rsb[i]; }
        float rinv = 1.0f / sqrtf(a);
        s_rinv = rinv;
        s_c = c * rinv;
    }
    __syncthreads();
    float rinv = s_rinv;
    g_fproj[b * D_PROJ + t]       = v1 * rinv;
    g_fproj[b * D_PROJ + t + 256] = v2 * rinv;
    if (t == 0) g_c[b] = s_c;
}

// ---------------- u_b = W^T f_b ------------------------------------------
__global__ void k_u(const float* __restrict__ W) {
    __shared__ float sf[D_PROJ];
    int b = blockIdx.y;
    int t = threadIdx.x;
    int d = blockIdx.x * 256 + t;
    sf[t]       = g_fproj[b * D_PROJ + t];
    sf[t + 256] = g_fproj[b * D_PROJ + t + 256];
    __syncthreads();
    float sum = 0.f;
    #pragma unroll 4
    for (int p = 0; p < D_PROJ; p++)
        sum = fmaf(sf[p], W[(size_t)p * D_IN + d], sum);
    g_u[b * D_IN + d] = sum;
}

// ---------------- flag unique idx rows + compact --------------------------
__global__ void k_flag(const int* __restrict__ idx) {
    int i = blockIdx.x * blockDim.x + threadIdx.x;
    if (i >= BB * KP1) return;
    int row = idx[i];
    if (atomicExch(&g_flag[row], 1) == 0) {
        int pos = atomicAdd(&g_count, 1);
        g_uniq[pos] = row;
        g_normsq[row] = 0.f;   // epilogue accumulates via atomicAdd
    }
}

// ---------------- A staging: global fp32 -> SMEM bf16 (swizzled) ----------
__device__ __forceinline__ void stage_A(const float* __restrict__ mem,
                                        const int* __restrict__ srow,
                                        uint32_t* sA, int koff, int t) {
    #pragma unroll
    for (int q = 0; q < 8; q++) {
        int i = q * 128 + t;            // 1024 granules = 128 rows x 8
        int row = i >> 3, g = i & 7;
        const float* pa = mem + (size_t)srow[row] * D_IN + koff + g * 8;
        float4 v0 = *(const float4*)pa;
        float4 v1 = *(const float4*)(pa + 4);
        uint4 w;
        w.x = pk_bf16x2(v0.x, v0.y); w.y = pk_bf16x2(v0.z, v0.w);
        w.z = pk_bf16x2(v1.x, v1.y); w.w = pk_bf16x2(v1.z, v1.w);
        *(uint4*)(sA + (row << 5) + ((g ^ (row & 7)) << 2)) = w;
    }
}

// ---------------- B staging: bf16 W -> SMEM via cp.async ------------------
__device__ __forceinline__ void stage_B(uint32_t sB_addr, int koff_e,
                                        int n0, int t) {
    const uint16_t* WB = (const uint16_t*)g_WB4;
    #pragma unroll
    for (int q = 0; q < 8; q++) {
        int i = q * 128 + t;
        int row = i >> 3, g = i & 7;
        const uint16_t* src = WB + (size_t)(n0 + row) * D_IN + koff_e + g * 8;
        uint32_t dst = sB_addr + (row << 7) + ((g ^ (row & 7)) << 4);
        CP_ASYNC16(dst, src);
    }
}

// ---------------- norms via mma.sync bf16 + ldmatrix ----------------------
__global__ void __launch_bounds__(128, 2)
k_norm_mma(const float* __restrict__ mem, const float* __restrict__ bias) {
    extern __shared__ uint32_t smu[];
    int cnt = g_count;
    int m0 = blockIdx.y * 128;
    if (m0 >= cnt) return;
    int n0 = blockIdx.x * 128;

    int t = threadIdx.x, lane = t & 31, warp = t >> 5;
    int wm = warp >> 1, wn = warp & 1;       // 2x2 warp grid
    int gid = lane >> 2, tig = lane & 3;
    int quad = lane >> 3, l7 = lane & 7;

    uint32_t sbase = smem_u32(smu);
    int*   srow  = (int*)((char*)smu + SROW_OFF);
    float* sbias = (float*)((char*)smu + SBIAS_OFF);
    {
        int g = m0 + t;
        srow[t]  = g_uniq[(g < cnt) ? g : m0];
        sbias[t] = bias[n0 + t];
    }
    __syncthreads();

    // per-lane ldmatrix row geometry (rows fixed across stages/ksteps)
    int a_row[4], b_row[4];
    int gsa = quad >> 1, gsb = quad & 1;
    #pragma unroll
    for (int mi = 0; mi < 4; mi++)
        a_row[mi] = wm * 64 + mi * 16 + (quad & 1) * 8 + l7;
    #pragma unroll
    for (int np = 0; np < 4; np++)
        b_row[np] = wn * 64 + np * 16 + (quad >> 1) * 8 + l7;

    float c[4][8][4];
    #pragma unroll
    for (int mi = 0; mi < 4; mi++)
        #pragma unroll
        for (int ni = 0; ni < 8; ni++)
            #pragma unroll
            for (int j = 0; j < 4; j++) c[mi][ni][j] = 0.f;

    // prologue: stage 0
    stage_A(mem, srow, smu + (A_OFF >> 2), 0, t);
    stage_B(sbase + B_OFF, 0, n0, t);
    CP_COMMIT();

    for (int s = 0; s < NST; s++) {
        int cur = s & 1;
        if (s + 1 < NST) {
            int nb = (s + 1) & 1;
            stage_A(mem, srow, smu + (A_OFF >> 2) + nb * (TILE_BYTES >> 2),
                    (s + 1) * KC, t);
            stage_B(sbase + B_OFF + nb * TILE_BYTES, (s + 1) * KC, n0, t);
            CP_COMMIT();
            CP_WAIT1();
        } else {
            CP_WAIT0();
        }
        __syncthreads();

        uint32_t abuf = sbase + A_OFF + cur * TILE_BYTES;
        uint32_t bbuf = sbase + B_OFF + cur * TILE_BYTES;
        #pragma unroll
        for (int ks = 0; ks < 4; ks++) {
            uint32_t a[4][4];
            #pragma unroll
            for (int mi = 0; mi < 4; mi++) {
                int r = a_row[mi];
                ldm4(a[mi], abuf + (r << 7) + ((((2 * ks + gsa) ^ (r & 7))) << 4));
            }
            #pragma unroll
            for (int np = 0; np < 4; np++) {
                uint32_t b[4];
                int r = b_row[np];
                ldm4(b, bbuf + (r << 7) + ((((2 * ks + gsb) ^ (r & 7))) << 4));
                #pragma unroll
                for (int mi = 0; mi < 4; mi++) {
                    mma16(c[mi][2 * np],     a[mi], b[0], b[1]);
                    mma16(c[mi][2 * np + 1], a[mi], b[2], b[3]);
                }
            }
        }
        __syncthreads();
    }

    // epilogue: (acc + bias)^2, quad-reduce across tig, atomicAdd per row
    #pragma unroll
    for (int mi = 0; mi < 4; mi++) {
        #pragma unroll
        for (int h = 0; h < 2; h++) {
            int m = wm * 64 + mi * 16 + gid + h * 8;
            float part = 0.f;
            #pragma unroll
            for (int ni = 0; ni < 8; ni++) {
                #pragma unroll
                for (int j = 0; j < 2; j++) {
                    int n = wn * 64 + ni * 8 + tig * 2 + j;
                    float v = c[mi][ni][h * 2 + j] + sbias[n];
                    part = fmaf(v, v, part);
                }
            }
            part += __shfl_xor_sync(0xffffffffu, part, 1);
            part += __shfl_xor_sync(0xffffffffu, part, 2);
            if (tig == 0 && m0 + m < cnt)
                atomicAdd(&g_normsq[srow[m]], part);
        }
    }
}

// ---------------- out[b,k] = (m.u_b + c_b) / (sqrt(normsq) * T) ----------
__global__ void k_out(const float* __restrict__ mem,
                      const int* __restrict__ idx,
                      float* __restrict__ out) {
    __shared__ float su[D_IN];
    int b = blockIdx.y;
    int kbase = blockIdx.x * 32;
    int t = threadIdx.x, lane = t & 31, warp = t >> 5;

    float4* su4 = (float4*)su;
    const float4* u4 = (const float4*)(g_u + (size_t)b * D_IN);
    su4[t]       = u4[t];
    su4[t + 256] = u4[t + 256];
    __syncthreads();
    float c = g_c[b];

    for (int j = 0; j < 4; j++) {
        int k = kbase + warp + 8 * j;
        int row = idx[b * KP1 + k];
        const float4* m4 = (const float4*)(mem + (size_t)row * D_IN);
        float sum = 0.f;
        #pragma unroll
        for (int i = 0; i < 16; i++) {
            float4 mv = m4[lane + i * 32];
            float4 uv = su4[lane + i * 32];
            sum += mv.x * uv.x + mv.y * uv.y + mv.z * uv.z + mv.w * uv.w;
        }
        #pragma unroll
        for (int o = 16; o > 0; o >>= 1) sum += __shfl_xor_sync(0xffffffffu, sum, o);
        if (lane == 0) {
            float num = sum + c;
            out[b * KP1 + k] = num / (sqrtf(g_normsq[row]) * TEMP);
        }
    }
}

// ---------------- momentum update (sequential i => JAX last-wins) --------
__global__ void k_update(const float* __restrict__ mem,
                         const float* __restrict__ feat,
                         const int* __restrict__ y,
                         float* __restrict__ newmem) {
    int d = blockIdx.x * blockDim.x + threadIdx.x;  // 0..2047
    for (int i = 0; i < BB; i++) {
        int row = y[i];
        newmem[(size_t)row * D_IN + d] =
            MOM * mem[(size_t)row * D_IN + d] + (1.0f - MOM) * feat[i * D_IN + d];
    }
}

// ---------------- launch -------------------------------------------------
extern "C" void kernel_launch(void* const* d_in, const int* in_sizes, int n_in,
                              void* d_out, int out_size) {
    const float* feat = (const float*)d_in[0];
    const int*   y    = (const int*)d_in[1];
    const int*   idx  = (const int*)d_in[2];
    const float* mem  = (const float*)d_in[3];
    const float* W    = (const float*)d_in[4];
    const float* bias = (const float*)d_in[5];

    float* out = (float*)d_out;
    float* newmem = out + (size_t)BB * KP1;

    // fork the 671MB copy onto a second captured stream so it overlaps compute
    cudaStream_t s1;
    cudaEvent_t e0, e1;
    cudaStreamCreateWithFlags(&s1, cudaStreamNonBlocking);
    cudaEventCreateWithFlags(&e0, cudaEventDisableTiming);
    cudaEventCreateWithFlags(&e1, cudaEventDisableTiming);
    cudaEventRecord(e0, 0);
    cudaStreamWaitEvent(s1, e0, 0);
    cudaMemcpyAsync(newmem, mem, (size_t)N_MEM * D_IN * sizeof(float),
                    cudaMemcpyDeviceToDevice, s1);
    cudaEventRecord(e1, s1);

    k_reset<<<(N_MEM + 255) / 256, 256>>>();
    k_prepW<<<D_PROJ, 256>>>(W);
    k_fproj<<<BB, 256>>>(feat, W, bias);
    {
        dim3 g(D_IN / 256, BB);
        k_u<<<g, 256>>>(W);
    }
    k_flag<<<(BB * KP1 + 255) / 256, 256>>>(idx);
    {
        cudaFuncSetAttribute(k_norm_mma,
                             cudaFuncAttributeMaxDynamicSharedMemorySize,
                             SMEM_BYTES);
        // worst case unique rows = 65536 -> 512 M-tiles; 4 N-tiles of 128
        dim3 g(4, 512);
        k_norm_mma<<<g, 128, SMEM_BYTES>>>(mem, bias);
    }
    {
        dim3 g(KP1 / 32, BB);
        k_out<<<g, 256>>>(mem, idx, out);
    }
    cudaStreamWaitEvent(0, e1, 0);
    k_update<<<D_IN / 256, 256>>>(mem, feat, y, newmem);

    cudaEventDestroy(e0);
    cudaEventDestroy(e1);
    cudaStreamDestroy(s1);
}